// round 5
// baseline (speedup 1.0000x reference)
#include <cuda_runtime.h>
#include <cuda_bf16.h>
#include <cstdint>

// Problem constants
#define BATCH 2
#define SEQ   2048
#define DIM   1024
#define HEADS 16
#define DK    64
#define CL    256
#define HID   512
#define MROWS (BATCH*SEQ)   // 4096

// ---------------- scratch (device globals; no allocation allowed) ----------------
__device__ float g_q[MROWS * DIM];
__device__ float g_k[MROWS * DIM];
__device__ float g_v[MROWS * DIM];
__device__ float g_x[MROWS * DIM];
__device__ float g_h[BATCH * HID];
__device__ float g_c[BATCH * DIM];

// ---------------- cond MLP ----------------
// h[b][j] = relu(sum_k cond[b][k] * Wc1[k][j] + bc1[j])
__global__ void cond_mlp1(const float* __restrict__ cond, const float* __restrict__ Wc1,
                          const float* __restrict__ bc1, float* __restrict__ h) {
    int b = blockIdx.x;
    int j = threadIdx.x;            // 512
    float acc = bc1[j];
    const float* cr = cond + b * CL;
    #pragma unroll 8
    for (int k = 0; k < CL; k++) acc = fmaf(cr[k], Wc1[k * HID + j], acc);
    h[b * HID + j] = acc > 0.f ? acc : 0.f;
}

// c[b][n] = sum_k h[b][k] * Wc2[k][n]
__global__ void cond_mlp2(const float* __restrict__ h, const float* __restrict__ Wc2,
                          float* __restrict__ c) {
    int b = blockIdx.x;
    int n = threadIdx.x;            // 1024
    float acc = 0.f;
    const float* hr = h + b * HID;
    #pragma unroll 8
    for (int k = 0; k < HID; k++) acc = fmaf(hr[k], Wc2[k * DIM + n], acc);
    c[b * DIM + n] = acc;
}

// ---------------- fp32 SGEMM: C[M,N] = A[M,K] @ W[K,N] + bias[n] (+ cb[row/S][n]) ----
#define GBM 128
#define GBN 128
#define GBK 8

__global__ __launch_bounds__(256, 2)
void sgemm_bias(const float* __restrict__ A, const float* __restrict__ W,
                const float* __restrict__ bias, const float* __restrict__ cb,
                float* __restrict__ C, int M, int N, int K, int S) {
    __shared__ float As[GBK][GBM + 4];   // [k][m], padded
    __shared__ float Bs[GBK][GBN];       // [k][n]

    const int tid  = threadIdx.x;        // 256
    const int trow = tid >> 4;           // 0..15
    const int tcol = tid & 15;           // 0..15
    const int bm = blockIdx.y * GBM;
    const int bn = blockIdx.x * GBN;

    const int arow = tid >> 1;           // 0..127
    const int acol = (tid & 1) << 2;     // 0 or 4
    const int brow = tid >> 5;           // 0..7
    const int bcol = (tid & 31) << 2;    // 0..124

    float acc[8][8];
    #pragma unroll
    for (int i = 0; i < 8; i++)
        #pragma unroll
        for (int j = 0; j < 8; j++) acc[i][j] = 0.f;

    for (int k0 = 0; k0 < K; k0 += GBK) {
        float4 av = *(const float4*)(A + (size_t)(bm + arow) * K + k0 + acol);
        As[acol + 0][arow] = av.x;
        As[acol + 1][arow] = av.y;
        As[acol + 2][arow] = av.z;
        As[acol + 3][arow] = av.w;
        float4 bv = *(const float4*)(W + (size_t)(k0 + brow) * N + bn + bcol);
        *(float4*)&Bs[brow][bcol] = bv;
        __syncthreads();

        #pragma unroll
        for (int k = 0; k < GBK; k++) {
            float ra[8], rb[8];
            #pragma unroll
            for (int i = 0; i < 8; i++) ra[i] = As[k][trow * 8 + i];
            #pragma unroll
            for (int j = 0; j < 8; j++) rb[j] = Bs[k][tcol * 8 + j];
            #pragma unroll
            for (int i = 0; i < 8; i++)
                #pragma unroll
                for (int j = 0; j < 8; j++)
                    acc[i][j] = fmaf(ra[i], rb[j], acc[i][j]);
        }
        __syncthreads();
    }

    #pragma unroll
    for (int i = 0; i < 8; i++) {
        const int row = bm + trow * 8 + i;
        const int batch = row / S;
        const float* cbr = cb ? (cb + (size_t)batch * N) : nullptr;
        #pragma unroll
        for (int j = 0; j < 8; j += 4) {
            const int col = bn + tcol * 8 + j;
            float4 o;
            o.x = acc[i][j + 0] + bias[col + 0];
            o.y = acc[i][j + 1] + bias[col + 1];
            o.z = acc[i][j + 2] + bias[col + 2];
            o.w = acc[i][j + 3] + bias[col + 3];
            if (cbr) {
                o.x += cbr[col + 0]; o.y += cbr[col + 1];
                o.z += cbr[col + 2]; o.w += cbr[col + 3];
            }
            *(float4*)(C + (size_t)row * N + col) = o;
        }
    }
}

// ---------------- flash attention (fp32, online softmax) ----------------
// Br=128 query rows per CTA, Bc=64 key rows per iteration, dk=64.
// 256 threads: ty=tid/16 owns 8 q-rows, tx=tid%16 owns 4 cols.
#define BR 128
#define BC 64
#define QP 65                    // smem pitch (floats)
#define FA_SMEM_FLOATS (BR*QP /*Q*/ + BC*QP /*K*/ + BC*QP /*V*/ + BR*QP /*P*/ + BR*17 /*red*/ + 3*BR)
#define FA_SMEM_BYTES  (FA_SMEM_FLOATS * 4)

__global__ __launch_bounds__(256, 2)
void flash_attn(const float* __restrict__ Qg, const float* __restrict__ Kg,
                const float* __restrict__ Vg, float* __restrict__ Og) {
    extern __shared__ float sm[];
    float* Qs   = sm;                    // [BR][QP]
    float* Ks   = Qs + BR * QP;          // [BC][QP]
    float* Vs   = Ks + BC * QP;          // [BC][QP]
    float* Ps   = Vs + BC * QP;          // [BR][QP]
    float* red  = Ps + BR * QP;          // [BR][17]
    float* mrow = red + BR * 17;         // [BR]
    float* lrow = mrow + BR;             // [BR]
    float* arow = lrow + BR;             // [BR]

    const int tid = threadIdx.x;
    const int ty = tid >> 4;             // 0..15
    const int tx = tid & 15;             // 0..15
    const int row0 = ty * 8;
    const int col0 = tx * 4;

    const int qb = blockIdx.x;           // 0..15
    const int bh = blockIdx.y;           // 0..31
    const int b = bh >> 4, h = bh & 15;
    const size_t base = (size_t)b * SEQ * DIM + h * DK;
    const int qbase = qb * BR;

    // load Q tile [BR x DK]
    #pragma unroll
    for (int i = 0; i < 8; i++) {
        int idx = tid + i * 256;         // 0..2047
        int r = idx >> 4;
        int c4 = (idx & 15) << 2;
        float4 v = *(const float4*)(Qg + base + (size_t)(qbase + r) * DIM + c4);
        float* d = Qs + r * QP + c4;
        d[0] = v.x; d[1] = v.y; d[2] = v.z; d[3] = v.w;
    }
    if (tid < BR) { mrow[tid] = -1e30f; lrow[tid] = 0.f; }

    float oacc[8][4];
    #pragma unroll
    for (int i = 0; i < 8; i++)
        #pragma unroll
        for (int j = 0; j < 4; j++) oacc[i][j] = 0.f;

    const float sc = 0.125f;             // 1/sqrt(64)

    for (int kb = 0; kb < SEQ / BC; kb++) {
        __syncthreads();                 // protect Ks/Vs reuse, cover first-iter Qs
        const int kbase = kb * BC;
        #pragma unroll
        for (int i = 0; i < 4; i++) {
            int idx = tid + i * 256;     // 0..1023
            int r = idx >> 4;
            int c4 = (idx & 15) << 2;
            float4 kv = *(const float4*)(Kg + base + (size_t)(kbase + r) * DIM + c4);
            float* kd = Ks + r * QP + c4;
            kd[0] = kv.x; kd[1] = kv.y; kd[2] = kv.z; kd[3] = kv.w;
            float4 vv = *(const float4*)(Vg + base + (size_t)(kbase + r) * DIM + c4);
            float* vd = Vs + r * QP + c4;
            vd[0] = vv.x; vd[1] = vv.y; vd[2] = vv.z; vd[3] = vv.w;
        }
        __syncthreads();

        // S = Q K^T (scaled later)
        float sacc[8][4];
        #pragma unroll
        for (int i = 0; i < 8; i++)
            #pragma unroll
            for (int j = 0; j < 4; j++) sacc[i][j] = 0.f;

        for (int d = 0; d < DK; d++) {
            float qv[8], kv[4];
            #pragma unroll
            for (int i = 0; i < 8; i++) qv[i] = Qs[(row0 + i) * QP + d];
            #pragma unroll
            for (int j = 0; j < 4; j++) kv[j] = Ks[(col0 + j) * QP + d];
            #pragma unroll
            for (int i = 0; i < 8; i++)
                #pragma unroll
                for (int j = 0; j < 4; j++)
                    sacc[i][j] = fmaf(qv[i], kv[j], sacc[i][j]);
        }

        // partial row max (of scaled scores)
        #pragma unroll
        for (int i = 0; i < 8; i++) {
            float mx = fmaxf(fmaxf(sacc[i][0], sacc[i][1]),
                             fmaxf(sacc[i][2], sacc[i][3]));
            red[(row0 + i) * 17 + tx] = mx * sc;
        }
        __syncthreads();
        if (tid < BR) {
            float mx = red[tid * 17];
            #pragma unroll
            for (int c = 1; c < 16; c++) mx = fmaxf(mx, red[tid * 17 + c]);
            float mold = mrow[tid];
            float mnew = fmaxf(mold, mx);
            mrow[tid] = mnew;
            arow[tid] = __expf(mold - mnew);
        }
        __syncthreads();

        // exp, write P to smem, partial row sums, rescale O
        #pragma unroll
        for (int i = 0; i < 8; i++) {
            const int r = row0 + i;
            const float mn = mrow[r];
            const float a  = arow[r];
            float rs = 0.f;
            #pragma unroll
            for (int j = 0; j < 4; j++) {
                float p = __expf(fmaf(sacc[i][j], sc, -mn));
                Ps[r * QP + col0 + j] = p;
                rs += p;
            }
            red[r * 17 + tx] = rs;
            #pragma unroll
            for (int j = 0; j < 4; j++) oacc[i][j] *= a;
        }
        __syncthreads();
        if (tid < BR) {
            float s0 = 0.f;
            #pragma unroll
            for (int c = 0; c < 16; c++) s0 += red[tid * 17 + c];
            lrow[tid] = lrow[tid] * arow[tid] + s0;
        }
        // no sync needed: O-gemm below touches only Ps (synced) and Vs

        // O += P V
        for (int k = 0; k < BC; k++) {
            float pv[8], vv[4];
            #pragma unroll
            for (int i = 0; i < 8; i++) pv[i] = Ps[(row0 + i) * QP + k];
            #pragma unroll
            for (int j = 0; j < 4; j++) vv[j] = Vs[k * QP + col0 + j];
            #pragma unroll
            for (int i = 0; i < 8; i++)
                #pragma unroll
                for (int j = 0; j < 4; j++)
                    oacc[i][j] = fmaf(pv[i], vv[j], oacc[i][j]);
        }
    }
    __syncthreads();                     // final lrow writes visible

    #pragma unroll
    for (int i = 0; i < 8; i++) {
        const int r = row0 + i;
        const float inv = 1.f / lrow[r];
        float4 o;
        o.x = oacc[i][0] * inv; o.y = oacc[i][1] * inv;
        o.z = oacc[i][2] * inv; o.w = oacc[i][3] * inv;
        *(float4*)(Og + base + (size_t)(qbase + r) * DIM + col0) = o;
    }
}

// ---------------- launcher ----------------
extern "C" void kernel_launch(void* const* d_in, const int* in_sizes, int n_in,
                              void* d_out, int out_size) {
    const float* query = (const float*)d_in[0];
    const float* key   = (const float*)d_in[1];
    const float* value = (const float*)d_in[2];
    const float* cond  = (const float*)d_in[3];
    const float* Wq = (const float*)d_in[4];
    const float* bq = (const float*)d_in[5];
    const float* Wk = (const float*)d_in[6];
    const float* bk = (const float*)d_in[7];
    const float* Wv = (const float*)d_in[8];
    const float* bv = (const float*)d_in[9];
    const float* Wo = (const float*)d_in[10];
    const float* bo = (const float*)d_in[11];
    const float* Wc1 = (const float*)d_in[12];
    const float* bc1 = (const float*)d_in[13];
    const float* Wc2 = (const float*)d_in[14];
    float* out = (float*)d_out;

    float *q, *k, *v, *x, *hb, *cb;
    cudaGetSymbolAddress((void**)&q,  g_q);
    cudaGetSymbolAddress((void**)&k,  g_k);
    cudaGetSymbolAddress((void**)&v,  g_v);
    cudaGetSymbolAddress((void**)&x,  g_x);
    cudaGetSymbolAddress((void**)&hb, g_h);
    cudaGetSymbolAddress((void**)&cb, g_c);

    cudaFuncSetAttribute(flash_attn, cudaFuncAttributeMaxDynamicSharedMemorySize,
                         FA_SMEM_BYTES);

    // cond MLP
    cond_mlp1<<<BATCH, HID>>>(cond, Wc1, bc1, hb);
    cond_mlp2<<<BATCH, DIM>>>(hb, Wc2, cb);

    // projections
    dim3 gg(DIM / GBN, MROWS / GBM);   // (8, 32)
    sgemm_bias<<<gg, 256>>>(query, Wq, bq, nullptr, q, MROWS, DIM, DIM, SEQ);
    sgemm_bias<<<gg, 256>>>(key,   Wk, bk, nullptr, k, MROWS, DIM, DIM, SEQ);
    sgemm_bias<<<gg, 256>>>(value, Wv, bv, cb,      v, MROWS, DIM, DIM, SEQ);

    // attention
    flash_attn<<<dim3(SEQ / BR, BATCH * HEADS), 256, FA_SMEM_BYTES>>>(q, k, v, x);

    // output projection
    sgemm_bias<<<gg, 256>>>(x, Wo, bo, nullptr, out, MROWS, DIM, DIM, SEQ);
}